// round 4
// baseline (speedup 1.0000x reference)
#include <cuda_runtime.h>
#include <cuda_bf16.h>
#include <cstdint>

#define NNODES 200000
#define CCH    256
#define VCD    48      // 16 * 3
#define MSEG   50000

// Scratch (allocation-free rule: __device__ globals)
__device__ float g_s_sum[MSEG * CCH];   // 51.2 MB
__device__ float g_v_sum[MSEG * VCD];   // 9.6 MB
__device__ float g_cnt[MSEG];

// ---------------------------------------------------------------------------
// Kernel 1: zero the scratch accumulators
// ---------------------------------------------------------------------------
__global__ void mp_zero_kernel() {
    int idx    = blockIdx.x * blockDim.x + threadIdx.x;
    int stride = gridDim.x * blockDim.x;
    const float4 z = make_float4(0.f, 0.f, 0.f, 0.f);
    const int nA = MSEG * CCH / 4;
    for (int i = idx; i < nA; i += stride) reinterpret_cast<float4*>(g_s_sum)[i] = z;
    const int nB = MSEG * VCD / 4;
    for (int i = idx; i < nB; i += stride) reinterpret_cast<float4*>(g_v_sum)[i] = z;
    const int nC = MSEG / 4;
    for (int i = idx; i < nC; i += stride) reinterpret_cast<float4*>(g_cnt)[i] = z;
}

// ---------------------------------------------------------------------------
// Kernel 2: scatter-sum s and v rows into per-motif accumulators.
// One warp per node row (grid-stride). float4 global loads, scalar REDs.
// NOTE: motif_batch arrives as int32 (JAX x64 disabled downgrades int64).
// ---------------------------------------------------------------------------
__global__ void mp_scatter_kernel(const float* __restrict__ s,
                                  const float* __restrict__ v,
                                  const int* __restrict__ seg) {
    int gwarp  = (blockIdx.x * blockDim.x + threadIdx.x) >> 5;
    int lane   = threadIdx.x & 31;
    int nwarps = (gridDim.x * blockDim.x) >> 5;

    for (int row = gwarp; row < NNODES; row += nwarps) {
        int m = seg[row];

        // s row: 256 floats = 64 float4; 32 lanes x 2
        const float4* srow = reinterpret_cast<const float4*>(s + (size_t)row * CCH);
        float* dsts = g_s_sum + (size_t)m * CCH;
#pragma unroll
        for (int i = 0; i < 2; i++) {
            int f4i = lane + 32 * i;
            float4 val = srow[f4i];
            int base = f4i * 4;
            atomicAdd(dsts + base + 0, val.x);
            atomicAdd(dsts + base + 1, val.y);
            atomicAdd(dsts + base + 2, val.z);
            atomicAdd(dsts + base + 3, val.w);
        }

        // v row: 48 floats = 12 float4; lanes 0..11
        if (lane < 12) {
            float4 val = reinterpret_cast<const float4*>(v + (size_t)row * VCD)[lane];
            float* dstv = g_v_sum + (size_t)m * VCD + lane * 4;
            atomicAdd(dstv + 0, val.x);
            atomicAdd(dstv + 1, val.y);
            atomicAdd(dstv + 2, val.z);
            atomicAdd(dstv + 3, val.w);
        }

        if (lane == 0) atomicAdd(&g_cnt[m], 1.0f);
    }
}

// ---------------------------------------------------------------------------
// Kernel 3: s_out[m, j] = (sum_k g_s_sum[m,k] * Ws[j,k]) / cnt[m] + bs[j]
// Tiled SGEMM: BM=128, BN=128, BK=16, 256 threads, 8x8 per thread.
// ---------------------------------------------------------------------------
#define BM 128
#define BN 128
#define BK 16
#define TM 8
#define TN 8

__global__ __launch_bounds__(256, 2)
void mp_gemm_kernel(const float* __restrict__ Ws,
                    const float* __restrict__ bs,
                    float* __restrict__ out_s) {
    __shared__ float sA[BK][BM + 4];
    __shared__ float sB[BK][BN + 4];

    const int tid = threadIdx.x;           // 0..255
    const int bm  = blockIdx.x * BM;
    const int bn  = blockIdx.y * BN;
    const int tx  = tid & 15;              // 0..15 -> N groups of 8
    const int ty  = tid >> 4;              // 0..15 -> M groups of 8

    float acc[TM][TN];
#pragma unroll
    for (int i = 0; i < TM; i++)
#pragma unroll
        for (int j = 0; j < TN; j++) acc[i][j] = 0.f;

    for (int k0 = 0; k0 < CCH; k0 += BK) {
        // Load A tile (g_s_sum[bm..bm+127, k0..k0+15]) transposed into sA[k][m]
#pragma unroll
        for (int it = 0; it < 2; it++) {
            int t  = tid + it * 256;       // 0..511
            int r  = t >> 2;               // row within tile 0..127
            int kc = (t & 3) * 4;          // k sub-col 0,4,8,12
            int grow = bm + r;
            float4 val = make_float4(0.f, 0.f, 0.f, 0.f);
            if (grow < MSEG)
                val = *reinterpret_cast<const float4*>(g_s_sum + (size_t)grow * CCH + k0 + kc);
            sA[kc + 0][r] = val.x;
            sA[kc + 1][r] = val.y;
            sA[kc + 2][r] = val.z;
            sA[kc + 3][r] = val.w;
        }
        // Load B tile (Ws[bn..bn+127, k0..k0+15]) transposed into sB[k][j]
#pragma unroll
        for (int it = 0; it < 2; it++) {
            int t  = tid + it * 256;
            int j  = t >> 2;
            int kc = (t & 3) * 4;
            float4 val = *reinterpret_cast<const float4*>(Ws + (size_t)(bn + j) * CCH + k0 + kc);
            sB[kc + 0][j] = val.x;
            sB[kc + 1][j] = val.y;
            sB[kc + 2][j] = val.z;
            sB[kc + 3][j] = val.w;
        }
        __syncthreads();

#pragma unroll
        for (int kk = 0; kk < BK; kk++) {
            float a[TM], b[TN];
#pragma unroll
            for (int i = 0; i < TM; i++) a[i] = sA[kk][ty * TM + i];
#pragma unroll
            for (int j = 0; j < TN; j++) b[j] = sB[kk][tx * TN + j];
#pragma unroll
            for (int i = 0; i < TM; i++)
#pragma unroll
                for (int j = 0; j < TN; j++) acc[i][j] = fmaf(a[i], b[j], acc[i][j]);
        }
        __syncthreads();
    }

    // Epilogue: /count, +bias
    float bvals[TN];
#pragma unroll
    for (int j = 0; j < TN; j++) bvals[j] = bs[bn + tx * TN + j];

#pragma unroll
    for (int i = 0; i < TM; i++) {
        int m = bm + ty * TM + i;
        if (m >= MSEG) continue;
        float inv = 1.0f / fmaxf(g_cnt[m], 1.0f);
        float* orow = out_s + (size_t)m * CCH + bn + tx * TN;
#pragma unroll
        for (int j = 0; j < TN; j++) orow[j] = acc[i][j] * inv + bvals[j];
    }
}

// ---------------------------------------------------------------------------
// Kernel 4: v_out[m, o, d] = (sum_c g_v_sum[m,c,d] * Wv[o,c]) / cnt[m] + bv[o]
// 16 motifs per block, stage their 48 sums in smem.
// ---------------------------------------------------------------------------
#define MOTIFS_PB 16

__global__ void mp_vtrans_kernel(const float* __restrict__ Wv,
                                 const float* __restrict__ bv,
                                 float* __restrict__ out_v) {
    __shared__ float sW[256];
    __shared__ float sb[16];
    __shared__ float sv[MOTIFS_PB * VCD];
    __shared__ float sc[MOTIFS_PB];

    const int tid = threadIdx.x;  // 256
    sW[tid] = Wv[tid];
    if (tid < 16) sb[tid] = bv[tid];

    const int m0 = blockIdx.x * MOTIFS_PB;   // 50000 = 16 * 3125, exact
    for (int i = tid; i < MOTIFS_PB * VCD; i += 256)
        sv[i] = g_v_sum[(size_t)m0 * VCD + i];
    if (tid < MOTIFS_PB)
        sc[tid] = 1.0f / fmaxf(g_cnt[m0 + tid], 1.0f);
    __syncthreads();

    for (int i = tid; i < MOTIFS_PB * VCD; i += 256) {
        int lm = i / VCD;
        int od = i - lm * VCD;
        int o  = od / 3;
        int d  = od - o * 3;
        float a = 0.f;
#pragma unroll
        for (int c = 0; c < 16; c++)
            a = fmaf(sW[o * 16 + c], sv[lm * VCD + c * 3 + d], a);
        out_v[(size_t)(m0 + lm) * VCD + od] = a * sc[lm] + sb[o];
    }
}

// ---------------------------------------------------------------------------
extern "C" void kernel_launch(void* const* d_in, const int* in_sizes, int n_in,
                              void* d_out, int out_size) {
    const float* s   = (const float*)d_in[0];       // [N, 256]
    const float* v   = (const float*)d_in[1];       // [N, 16, 3]
    const int*   seg = (const int*)d_in[2];         // [N] int32 (JAX x64-off)
    const float* Ws  = (const float*)d_in[3];       // [256, 256]
    const float* bs  = (const float*)d_in[4];       // [256]
    const float* Wv  = (const float*)d_in[5];       // [16, 16]
    const float* bv  = (const float*)d_in[6];       // [16]

    float* out_s = (float*)d_out;                        // [M, 256]
    float* out_v = (float*)d_out + (size_t)MSEG * CCH;   // [M, 16, 3]

    mp_zero_kernel<<<2048, 256>>>();
    mp_scatter_kernel<<<4096, 256>>>(s, v, seg);

    dim3 ggrid((MSEG + BM - 1) / BM, CCH / BN);          // (391, 2)
    mp_gemm_kernel<<<ggrid, 256>>>(Ws, bs, out_s);

    mp_vtrans_kernel<<<MSEG / MOTIFS_PB, 256>>>(Wv, bv, out_v);
}